// round 15
// baseline (speedup 1.0000x reference)
#include <cuda_runtime.h>
#include <cstdint>

#define BDIM 256
#define TDIM 1024
#define U    32
#define UNF  6
#define EPSV 1e-8f
#define AMAX 18
#define SMAX 32
#define SLOTMAX 8
#define NRMAX 16
#define FULLM 0xffffffffu
#define NTICK (TDIM * (BDIM / 8))   // 32768 tickets, 8 batch-rows each

// 64 MB scratch: precomputed sensory (num, den) per (b,t,unit)
__device__ float2 g_sens[(size_t)BDIM * TDIM * U];
// per-timestep completion counters (32 tickets per t)
__device__ int g_cnt[TDIM];

// per-column sparse recurrent lists (tanh form), layout [k*U + col] — fallback
__device__ int   g_asrc[AMAX * U];
__device__ float g_aa[AMAX * U], g_ab[AMAX * U], g_aweh[AMAX * U], g_awdh[AMAX * U];
__device__ float g_anum0[U], g_aden0[U];
__device__ int   g_na;

// source-side tanh scheme: lane i computes tv[s] = tanh(ca[s]*v_i - cb[s]) for its
// out-edges; dest j, round r gathers tv[r % SLOTS] from lane g_glane2[r*U+j].
__device__ float g_ca2[SLOTMAX * U], g_cb2[SLOTMAX * U];
__device__ int   g_glane2[NRMAX * U];
__device__ float g_gwe2[NRMAX * U], g_gwd2[NRMAX * U];
__device__ int   g_slots, g_rounds2, g_srcok;

// per-column sparse sensory lists (tanh form)
__device__ int   g_ssrc[SMAX * U];
__device__ float g_sa[SMAX * U], g_sb[SMAX * U], g_sweh[SMAX * U], g_swdh[SMAX * U];
__device__ float g_snum0[U], g_sden0[U];
__device__ int   g_ns;

__device__ __forceinline__ float tanhf_a(float x) {
    float r; asm("tanh.approx.f32 %0, %1;" : "=f"(r) : "f"(x)); return r;
}
__device__ __forceinline__ float rcpf(float x) {
    float r; asm("rcp.approx.ftz.f32 %0, %1;" : "=f"(r) : "f"(x)); return r;
}
__device__ __forceinline__ int ld_acq(const int* p) {
    int v; asm volatile("ld.acquire.gpu.global.b32 %0, [%1];" : "=r"(v) : "l"(p)); return v;
}

// ---------------------------------------------------------------------------
// Setup. sigmoid(s(v-mu)) = 0.5 + 0.5*tanh(a*v - b); halves fold into num0/den0.
// Parallel source-slot assignment with ROTATION decorrelation:
//   Phase A (warp 2, lane = source i): out-degree -> warp-reduce maxod -> pick
//     S (4 or 8); k-th out-edge of i -> slot (k + i) % S (distinct per source,
//     spread per dest; fixes R14's rank-0 slot pileup at low dest ids).
//   Phase B (warp 0, lane = dest j): edge with slot s -> round r = s + S*c[j][s]
//     (invariant r % S == s). r >= NRMAX -> fail -> R4 fallback body.
// ---------------------------------------------------------------------------
__global__ void __launch_bounds__(1024) setup_kernel(
    const int* __restrict__ spm, const float* __restrict__ wsyn,
    const float* __restrict__ mu, const float* __restrict__ sg,
    const float* __restrict__ er,
    const int* __restrict__ ssm, const float* __restrict__ sw,
    const float* __restrict__ smu, const float* __restrict__ ssg,
    const float* __restrict__ ser)
{
    __shared__ int   s_m[1024]; __shared__ float s_w[1024], s_mu[1024], s_sg[1024], s_er[1024];
    __shared__ int   t_m[1024]; __shared__ float t_w[1024], t_mu[1024], t_sg[1024], t_er[1024];
    __shared__ int   s_slot[1024];
    __shared__ int   s_S, s_failA;
    int tid = threadIdx.x;
    g_cnt[tid] = 0;
    s_m[tid] = spm[tid]; s_w[tid] = wsyn[tid]; s_mu[tid] = mu[tid];
    s_sg[tid] = sg[tid]; s_er[tid] = er[tid];
    t_m[tid] = ssm[tid]; t_w[tid] = sw[tid];  t_mu[tid] = smu[tid];
    t_sg[tid] = ssg[tid]; t_er[tid] = ser[tid];

    // parallel pre-clear of source-scheme arrays (assigners write only hits)
    if (tid < SLOTMAX * U) { g_ca2[tid] = 0.f; g_cb2[tid] = 0.f; }
    if (tid < NRMAX * U)   { g_glane2[tid] = 0; g_gwe2[tid] = 0.f; g_gwd2[tid] = 0.f; }
    if (tid == 0) { s_S = 4; s_failA = 0; }
    __syncthreads();

    if (tid < 32) {                       // fallback recurrent lists, column j = tid
        int j = tid, cnt = 0;
        float n0 = 0.f, d0 = 0.f;
        for (int i = 0; i < U; i++) {
            int idx = i * U + j;
            if (s_m[idx] != 0 && cnt < AMAX) {
                float a = 0.5f * s_sg[idx];
                float weh = 0.5f * s_w[idx] * s_er[idx];
                float wdh = 0.5f * s_w[idx];
                g_asrc[cnt * U + j] = i;
                g_aa[cnt * U + j]   = a;
                g_ab[cnt * U + j]   = a * s_mu[idx];
                g_aweh[cnt * U + j] = weh;
                g_awdh[cnt * U + j] = wdh;
                n0 += weh; d0 += wdh;
                cnt++;
            }
        }
        for (int k = cnt; k < AMAX; k++) {
            g_asrc[k * U + j] = 0;
            g_aa[k * U + j] = 0.f; g_ab[k * U + j] = 0.f;
            g_aweh[k * U + j] = 0.f; g_awdh[k * U + j] = 0.f;
        }
        g_anum0[j] = n0; g_aden0[j] = d0;
        int m = cnt;
        #pragma unroll
        for (int o = 16; o > 0; o >>= 1) m = max(m, __shfl_xor_sync(FULLM, m, o));
        if (j == 0) g_na = m;
    } else if (tid < 64) {                // sensory lists, column j = tid-32
        int j = tid - 32, cnt = 0;
        float n0 = 0.f, d0 = 0.f;
        for (int i = 0; i < U; i++) {
            int idx = i * U + j;
            if (t_m[idx] != 0 && cnt < SMAX) {
                float a = 0.5f * t_sg[idx];
                float weh = 0.5f * t_w[idx] * t_er[idx];
                float wdh = 0.5f * t_w[idx];
                g_ssrc[cnt * U + j] = i;
                g_sa[cnt * U + j]   = a;
                g_sb[cnt * U + j]   = a * t_mu[idx];
                g_sweh[cnt * U + j] = weh;
                g_swdh[cnt * U + j] = wdh;
                n0 += weh; d0 += wdh;
                cnt++;
            }
        }
        for (int k = cnt; k < SMAX; k++) {
            g_ssrc[k * U + j] = 0;
            g_sa[k * U + j] = 0.f; g_sb[k * U + j] = 0.f;
            g_sweh[k * U + j] = 0.f; g_swdh[k * U + j] = 0.f;
        }
        g_snum0[j] = n0; g_sden0[j] = d0;
        int m = cnt;
        #pragma unroll
        for (int o = 16; o > 0; o >>= 1) m = max(m, __shfl_xor_sync(FULLM, m, o));
        if (j == 0) g_ns = m;
    } else if (tid < 96) {                // Phase A: source lane i = tid-64
        int i = tid - 64;
        // out-degree
        int od = 0;
        for (int j = 0; j < U; j++) if (s_m[i * U + j] != 0) od++;
        int m = od;
        #pragma unroll
        for (int o = 16; o > 0; o >>= 1) m = max(m, __shfl_xor_sync(FULLM, m, o));
        int S = (m <= 4) ? 4 : 8;        // uniform across warp (reduced m)
        if (i == 0) {
            s_S = S;
            if (m > SLOTMAX) s_failA = 1;
        }
        // rotated slot assignment: k-th out-edge -> slot (k + i) % S
        int k = 0;
        for (int j = 0; j < U; j++) {
            int idx = i * U + j;
            if (s_m[idx] != 0) {
                if (k < SLOTMAX) {
                    int s = (k + i) % S;
                    s_slot[idx] = s;
                    float a = 0.5f * s_sg[idx];
                    g_ca2[s * U + i] = a;
                    g_cb2[s * U + i] = a * s_mu[idx];
                }
                k++;
            }
        }
    }
    __syncthreads();

    if (tid < 32) {                       // Phase B: dest lane j = tid
        int j = tid;
        int S = s_S;
        int fail = s_failA;
        int c[SLOTMAX];
        #pragma unroll
        for (int s = 0; s < SLOTMAX; s++) c[s] = 0;
        int maxR = 0;
        for (int i = 0; i < U; i++) {
            int idx = i * U + j;
            if (s_m[idx] == 0) continue;
            int s = s_slot[idx];
            int r = s + S * c[s];
            c[s]++;
            if (r >= NRMAX) { fail = 1; continue; }
            g_glane2[r * U + j] = i;
            g_gwe2[r * U + j]  = 0.5f * s_w[idx] * s_er[idx];
            g_gwd2[r * U + j]  = 0.5f * s_w[idx];
            if (r + 1 > maxR) maxR = r + 1;
        }
        int m = maxR, f = fail;
        #pragma unroll
        for (int o = 16; o > 0; o >>= 1) {
            m = max(m, __shfl_xor_sync(FULLM, m, o));
            f = max(f, __shfl_xor_sync(FULLM, f, o));
        }
        if (j == 0) { g_rounds2 = m; g_srcok = (f == 0); g_slots = S; }
    }
}

// ---------------------------------------------------------------------------
// Fused producer/consumer kernel (655us layout):
// Blocks 0..127: warps 0,1 = scan (batches 2*bid, 2*bid+1), warps 2,3,6,7 = sens,
//                warps 4,5 exit. Blocks >=128: all 8 warps = sens.
// ---------------------------------------------------------------------------
__device__ void sens_warp(
    int sw, int nw, int warp, int lane, float* smem,
    const float* __restrict__ x,
    const float* __restrict__ d1w, const float* __restrict__ d1b,
    const float* __restrict__ d2b,
    const float* __restrict__ iw,  const float* __restrict__ ib)
{
    float* sh_w2t = smem;                       // [32][132]
    float* sh_h1  = smem + 32 * 132 + warp * 1024;   // [8][128] per warp
    float* sh_in  = smem + 32 * 132 + 8 * 1024 + warp * 256; // [8][32] per warp

    float wa[4], wb[4], bb[4];
    #pragma unroll
    for (int c = 0; c < 4; c++) {
        int k = c * 32 + lane;
        wa[c] = d1w[k]; wb[c] = d1w[128 + k]; bb[c] = d1b[k];
    }
    float dbl = d2b[lane], iwl = iw[lane], ibl = ib[lane];
    float n0 = g_snum0[lane], d0 = g_sden0[lane];
    int ns = g_ns;

    for (int q = sw; q < NTICK; q += nw) {
        int t  = q >> 5;
        int b0 = (q & 31) << 3;

        float2 xv = make_float2(0.f, 0.f);
        if (lane < 8) xv = ((const float2*)x)[(size_t)(b0 + lane) * TDIM + t];

        #pragma unroll
        for (int r = 0; r < 8; r++) {
            float x0 = __shfl_sync(FULLM, xv.x, r);
            float x1 = __shfl_sync(FULLM, xv.y, r);
            #pragma unroll
            for (int c = 0; c < 4; c++) {
                int k = c * 32 + lane;
                sh_h1[r * 128 + k] = fmaxf(fmaf(x0, wa[c], fmaf(x1, wb[c], bb[c])), 0.f);
            }
        }
        __syncwarp();

        float acc[8];
        #pragma unroll
        for (int r = 0; r < 8; r++) acc[r] = dbl;
        #pragma unroll 8
        for (int kq = 0; kq < 32; kq++) {
            float4 w4 = *(const float4*)&sh_w2t[lane * 132 + kq * 4];
            #pragma unroll
            for (int r = 0; r < 8; r++) {
                float4 h4 = *(const float4*)&sh_h1[r * 128 + kq * 4];
                acc[r] = fmaf(h4.x, w4.x, acc[r]);
                acc[r] = fmaf(h4.y, w4.y, acc[r]);
                acc[r] = fmaf(h4.z, w4.z, acc[r]);
                acc[r] = fmaf(h4.w, w4.w, acc[r]);
            }
        }
        #pragma unroll
        for (int r = 0; r < 8; r++) sh_in[r * 32 + lane] = fmaf(acc[r], iwl, ibl);
        __syncwarp();

        float num[8], den[8];
        #pragma unroll
        for (int r = 0; r < 8; r++) { num[r] = n0; den[r] = d0; }
        for (int k = 0; k < ns; k++) {
            int   src = g_ssrc[k * U + lane];
            float a   = g_sa[k * U + lane];
            float b   = g_sb[k * U + lane];
            float weh = g_sweh[k * U + lane];
            float wdh = g_swdh[k * U + lane];
            #pragma unroll
            for (int r = 0; r < 8; r++) {
                float tk = tanhf_a(fmaf(a, sh_in[r * 32 + src], -b));
                num[r] = fmaf(weh, tk, num[r]);
                den[r] = fmaf(wdh, tk, den[r]);
            }
        }
        #pragma unroll
        for (int r = 0; r < 8; r++)
            g_sens[((size_t)(b0 + r) * TDIM + t) * U + lane] = make_float2(num[r], den[r]);

        __threadfence();
        if (lane == 0) atomicAdd(&g_cnt[t], 1);
        __syncwarp();
    }
}

__device__ __forceinline__ void verify8(int base) {
    for (;;) {
        int ok = 1;
        #pragma unroll
        for (int i = 0; i < 8; i++)
            ok &= (ld_acq(&g_cnt[base + i]) == 32);
        if (ok) return;
        __nanosleep(200);
    }
}

// Source-side tanh scan: lane computes SLOTS tanh from LOCAL v (no shfl wait),
// then one gather wave of NR shfls delivers finished tanh values.
template <int SLOTS, int NR>
__device__ void scan_src(
    int lane, int batch,
    const float* __restrict__ gleak, const float* __restrict__ vleak,
    const float* __restrict__ cm,
    const float* __restrict__ ow, const float* __restrict__ ob,
    float* __restrict__ out)
{
    float gl   = gleak[lane];
    float cmt  = cm[lane] * (float)UNF;
    float gv   = gl * vleak[lane];
    float dcst = cmt + gl + EPSV + g_aden0[lane];
    float ncst = g_anum0[lane];

    float ca[SLOTS], cb[SLOTS];
    #pragma unroll
    for (int s = 0; s < SLOTS; s++) {
        ca[s] = g_ca2[s * U + lane];
        cb[s] = g_cb2[s * U + lane];
    }
    int gl_[NR]; float gwe[NR], gwd[NR];
    #pragma unroll
    for (int r = 0; r < NR; r++) {
        gl_[r] = g_glane2[r * U + lane];
        gwe[r] = g_gwe2[r * U + lane];
        gwd[r] = g_gwd2[r * U + lane];
    }

    const float2* sp = g_sens + (size_t)batch * TDIM * U + lane;

    verify8(0);
    float2 sv = sp[0];
    float v = 0.f;

    for (int t = 0; t < TDIM; t++) {
        if ((t & 7) == 0 && t + 8 < TDIM) verify8(t + 8);
        int tn = (t + 1 < TDIM) ? (t + 1) : t;
        float2 nxt = sp[(size_t)tn * U];

        float nb = sv.x + ncst;
        float db = sv.y + dcst;

        #pragma unroll
        for (int u = 0; u < UNF; u++) {
            float p = fmaf(cmt, v, gv);
            // local tanh of out-edges: args ready at cycle 0
            float tv[SLOTS];
            #pragma unroll
            for (int s = 0; s < SLOTS; s++)
                tv[s] = tanhf_a(fmaf(ca[s], v, -cb[s]));
            // one gather wave: finished tanh values from source lanes
            float tk[NR];
            #pragma unroll
            for (int r = 0; r < NR; r++)
                tk[r] = __shfl_sync(FULLM, tv[r % SLOTS], gl_[r]);

            float nch[4], dch[4];
            nch[0] = p + nb; nch[1] = 0.f; nch[2] = 0.f; nch[3] = 0.f;
            dch[0] = db;     dch[1] = 0.f; dch[2] = 0.f; dch[3] = 0.f;
            #pragma unroll
            for (int r = 0; r < NR; r++) {
                nch[r & 3] = fmaf(gwe[r], tk[r], nch[r & 3]);
                dch[r & 3] = fmaf(gwd[r], tk[r], dch[r & 3]);
            }
            float num = (nch[0] + nch[1]) + (nch[2] + nch[3]);
            float den = (dch[0] + dch[1]) + (dch[2] + dch[3]);
            v = num * rcpf(den);
        }
        sv = nxt;
    }

    if (lane == 0) out[batch] = fmaf(v, ow[0], ob[0]);
}

// R4 fallback body
template <int NA>
__device__ void scan_body(
    int lane, int batch,
    const float* __restrict__ gleak, const float* __restrict__ vleak,
    const float* __restrict__ cm,
    const float* __restrict__ ow, const float* __restrict__ ob,
    float* __restrict__ out)
{
    float gl   = gleak[lane];
    float cmt  = cm[lane] * (float)UNF;
    float gv   = gl * vleak[lane];
    float dcst = cmt + gl + EPSV + g_aden0[lane];
    float ncst = g_anum0[lane];

    int src[NA]; float a[NA], b[NA], weh[NA], wdh[NA];
    #pragma unroll
    for (int k = 0; k < NA; k++) {
        src[k] = g_asrc[k * U + lane];
        a[k]   = g_aa[k * U + lane];
        b[k]   = g_ab[k * U + lane];
        weh[k] = g_aweh[k * U + lane];
        wdh[k] = g_awdh[k * U + lane];
    }

    const float2* sp = g_sens + (size_t)batch * TDIM * U + lane;

    verify8(0);
    float2 sv = sp[0];
    float v = 0.f;

    for (int t = 0; t < TDIM; t++) {
        if ((t & 7) == 0 && t + 8 < TDIM) verify8(t + 8);
        int tn = (t + 1 < TDIM) ? (t + 1) : t;
        float2 nxt = sp[(size_t)tn * U];

        float nb = sv.x + ncst;
        float db = sv.y + dcst;

        #pragma unroll
        for (int u = 0; u < UNF; u++) {
            float p = fmaf(cmt, v, gv);
            float tk[NA];
            #pragma unroll
            for (int k = 0; k < NA; k++) {
                float vs = __shfl_sync(FULLM, v, src[k]);
                tk[k] = tanhf_a(fmaf(a[k], vs, -b[k]));
            }
            float nch[4], dch[4];
            nch[0] = p + nb; nch[1] = 0.f; nch[2] = 0.f; nch[3] = 0.f;
            dch[0] = db;     dch[1] = 0.f; dch[2] = 0.f; dch[3] = 0.f;
            #pragma unroll
            for (int k = 0; k < NA; k++) {
                nch[k & 3] = fmaf(weh[k], tk[k], nch[k & 3]);
                dch[k & 3] = fmaf(wdh[k], tk[k], dch[k & 3]);
            }
            float num = (nch[0] + nch[1]) + (nch[2] + nch[3]);
            float den = (dch[0] + dch[1]) + (dch[2] + dch[3]);
            v = num * rcpf(den);
        }
        sv = nxt;
    }

    if (lane == 0) out[batch] = fmaf(v, ow[0], ob[0]);
}

__global__ void __launch_bounds__(256) fused_kernel(
    const float* __restrict__ x,
    const float* __restrict__ d1w, const float* __restrict__ d1b,
    const float* __restrict__ d2w, const float* __restrict__ d2b,
    const float* __restrict__ iw,  const float* __restrict__ ib,
    const float* __restrict__ gleak, const float* __restrict__ vleak,
    const float* __restrict__ cm,
    const float* __restrict__ ow, const float* __restrict__ ob,
    float* __restrict__ out)
{
    extern __shared__ float smem[];
    int tid = threadIdx.x, warp = tid >> 5, lane = tid & 31;

    for (int i = tid; i < 128 * 32; i += 256) {
        int k = i >> 5, j = i & 31;
        smem[j * 132 + k] = d2w[i];
    }
    __syncthreads();

    bool scanBlk = (blockIdx.x < 128);
    if (scanBlk && warp < 2) {
        int batch = blockIdx.x * 2 + warp;
        int ok = g_srcok, sl = g_slots, rr = g_rounds2;
        if (ok && sl == 4) {
            if      (rr <= 8)  scan_src<4, 8 >(lane, batch, gleak, vleak, cm, ow, ob, out);
            else if (rr <= 12) scan_src<4, 12>(lane, batch, gleak, vleak, cm, ow, ob, out);
            else               scan_src<4, 16>(lane, batch, gleak, vleak, cm, ow, ob, out);
        } else if (ok && sl == 8) {
            if (rr <= 12)      scan_src<8, 12>(lane, batch, gleak, vleak, cm, ow, ob, out);
            else               scan_src<8, 16>(lane, batch, gleak, vleak, cm, ow, ob, out);
        } else {
            int na = g_na;
            if      (na <= 4)  scan_body<4 >(lane, batch, gleak, vleak, cm, ow, ob, out);
            else if (na <= 6)  scan_body<6 >(lane, batch, gleak, vleak, cm, ow, ob, out);
            else if (na <= 8)  scan_body<8 >(lane, batch, gleak, vleak, cm, ow, ob, out);
            else if (na <= 10) scan_body<10>(lane, batch, gleak, vleak, cm, ow, ob, out);
            else if (na <= 12) scan_body<12>(lane, batch, gleak, vleak, cm, ow, ob, out);
            else               scan_body<18>(lane, batch, gleak, vleak, cm, ow, ob, out);
        }
    } else if (scanBlk) {
        if (warp == 4 || warp == 5) return;     // keep SMSP 0/1 for scan warps
        int idx = (warp >= 6) ? (warp - 4) : (warp - 2);  // {2,3,6,7} -> {0,1,2,3}
        int sw = blockIdx.x * 4 + idx;
        int nw = 128 * 4 + (gridDim.x - 128) * 8;
        sens_warp(sw, nw, warp, lane, smem, x, d1w, d1b, d2b, iw, ib);
    } else {
        int sw = 128 * 4 + (blockIdx.x - 128) * 8 + warp;
        int nw = 128 * 4 + (gridDim.x - 128) * 8;
        sens_warp(sw, nw, warp, lane, smem, x, d1w, d1b, d2b, iw, ib);
    }
}

// ---------------------------------------------------------------------------
extern "C" void kernel_launch(void* const* d_in, const int* in_sizes, int n_in,
                              void* d_out, int out_size)
{
    const float* x    = (const float*)d_in[0];
    const float* d1w  = (const float*)d_in[1];
    const float* d1b  = (const float*)d_in[2];
    const float* d2w  = (const float*)d_in[3];
    const float* d2b  = (const float*)d_in[4];
    const float* iw   = (const float*)d_in[5];
    const float* ib   = (const float*)d_in[6];
    const float* ow   = (const float*)d_in[7];
    const float* ob   = (const float*)d_in[8];
    const float* gle  = (const float*)d_in[9];
    const float* vle  = (const float*)d_in[10];
    const float* cmv  = (const float*)d_in[11];
    const float* wsyn = (const float*)d_in[12];
    const float* muv  = (const float*)d_in[13];
    const float* sgv  = (const float*)d_in[14];
    const float* erv  = (const float*)d_in[15];
    const float* swv  = (const float*)d_in[16];
    const float* smuv = (const float*)d_in[17];
    const float* ssgv = (const float*)d_in[18];
    const float* serv = (const float*)d_in[19];
    const int*   spm  = (const int*)d_in[20];
    const int*   ssm  = (const int*)d_in[21];

    int nsm = 148;
    cudaDeviceGetAttribute(&nsm, cudaDevAttrMultiProcessorCount, 0);
    int blocks = (nsm > 128) ? nsm : 129;   // >=129 so at least 1 all-sens block

    const int smemBytes = (32 * 132 + 8 * 1024 + 8 * 256) * sizeof(float); // ~57.5 KB
    cudaFuncSetAttribute(fused_kernel, cudaFuncAttributeMaxDynamicSharedMemorySize, smemBytes);

    setup_kernel<<<1, 1024>>>(spm, wsyn, muv, sgv, erv, ssm, swv, smuv, ssgv, serv);
    fused_kernel<<<blocks, 256, smemBytes>>>(x, d1w, d1b, d2w, d2b, iw, ib,
                                             gle, vle, cmv, ow, ob, (float*)d_out);
}

// round 16
// speedup vs baseline: 1.2092x; 1.2092x over previous
#include <cuda_runtime.h>
#include <cstdint>

#define BDIM 256
#define TDIM 1024
#define U    32
#define UNF  6
#define EPSV 1e-8f
#define AMAX 18
#define SMAX 32
#define SLOTMAX 8
#define NRMAX 16
#define FULLM 0xffffffffu
#define NTICK (TDIM * (BDIM / 8))   // 32768 tickets, 8 batch-rows each

// 64 MB scratch: precomputed sensory (num, den) per (b,t,unit)
__device__ float2 g_sens[(size_t)BDIM * TDIM * U];
// per-timestep completion counters (32 tickets per t)
__device__ int g_cnt[TDIM];

// per-column sparse recurrent lists (tanh form), layout [k*U + col] — fallback
__device__ int   g_asrc[AMAX * U];
__device__ float g_aa[AMAX * U], g_ab[AMAX * U], g_aweh[AMAX * U], g_awdh[AMAX * U];
__device__ float g_anum0[U], g_aden0[U];
__device__ int   g_na;

// source-side tanh scheme: lane i computes tv[s] = tanh(ca[s]*v_i - cb[s]) for its
// out-edges; dest j, round r gathers tv[r % SLOTS] from lane g_glane2[r*U+j].
__device__ float g_ca2[SLOTMAX * U], g_cb2[SLOTMAX * U];
__device__ int   g_glane2[NRMAX * U];
__device__ float g_gwe2[NRMAX * U], g_gwd2[NRMAX * U];
__device__ int   g_slots, g_rounds2, g_srcok;

// per-column sparse sensory lists (tanh form)
__device__ int   g_ssrc[SMAX * U];
__device__ float g_sa[SMAX * U], g_sb[SMAX * U], g_sweh[SMAX * U], g_swdh[SMAX * U];
__device__ float g_snum0[U], g_sden0[U];
__device__ int   g_ns;

__device__ __forceinline__ float tanhf_a(float x) {
    float r; asm("tanh.approx.f32 %0, %1;" : "=f"(r) : "f"(x)); return r;
}
__device__ __forceinline__ float rcpf(float x) {
    float r; asm("rcp.approx.ftz.f32 %0, %1;" : "=f"(r) : "f"(x)); return r;
}
__device__ __forceinline__ int ld_acq(const int* p) {
    int v; asm volatile("ld.acquire.gpu.global.b32 %0, [%1];" : "=r"(v) : "l"(p)); return v;
}

// ---------------------------------------------------------------------------
// Setup. sigmoid(s(v-mu)) = 0.5 + 0.5*tanh(a*v - b); halves fold into num0/den0.
// tid==64 runs the R13 greedy source-slot assignment, but with BITMASK state:
//   roundUsed: 16-bit mask; slotUsed[i]: 4-bit nibble in shared s_su[32].
//   excl = (su * 0x1111) & 0xFFFF spreads slot bits to all rounds r%4==s.
//   cand = ~roundUsed & ~excl; r = ffs(cand)-1  (smallest free round — identical
//   assignment to the R13 serial greedy that measured fused=627us).
// ---------------------------------------------------------------------------
__global__ void __launch_bounds__(1024) setup_kernel(
    const int* __restrict__ spm, const float* __restrict__ wsyn,
    const float* __restrict__ mu, const float* __restrict__ sg,
    const float* __restrict__ er,
    const int* __restrict__ ssm, const float* __restrict__ sw,
    const float* __restrict__ smu, const float* __restrict__ ssg,
    const float* __restrict__ ser)
{
    __shared__ int   s_m[1024]; __shared__ float s_w[1024], s_mu[1024], s_sg[1024], s_er[1024];
    __shared__ int   t_m[1024]; __shared__ float t_w[1024], t_mu[1024], t_sg[1024], t_er[1024];
    __shared__ int   s_su[32];
    int tid = threadIdx.x;
    g_cnt[tid] = 0;
    s_m[tid] = spm[tid]; s_w[tid] = wsyn[tid]; s_mu[tid] = mu[tid];
    s_sg[tid] = sg[tid]; s_er[tid] = er[tid];
    t_m[tid] = ssm[tid]; t_w[tid] = sw[tid];  t_mu[tid] = smu[tid];
    t_sg[tid] = ssg[tid]; t_er[tid] = ser[tid];

    // parallel pre-clear of source-scheme arrays (assigner writes only hits)
    if (tid < SLOTMAX * U) { g_ca2[tid] = 0.f; g_cb2[tid] = 0.f; }
    if (tid < NRMAX * U)   { g_glane2[tid] = 0; g_gwe2[tid] = 0.f; g_gwd2[tid] = 0.f; }
    if (tid < 32) s_su[tid] = 0;
    __syncthreads();

    if (tid < 32) {                       // fallback recurrent lists, column j = tid
        int j = tid, cnt = 0;
        float n0 = 0.f, d0 = 0.f;
        for (int i = 0; i < U; i++) {
            int idx = i * U + j;
            if (s_m[idx] != 0 && cnt < AMAX) {
                float a = 0.5f * s_sg[idx];
                float weh = 0.5f * s_w[idx] * s_er[idx];
                float wdh = 0.5f * s_w[idx];
                g_asrc[cnt * U + j] = i;
                g_aa[cnt * U + j]   = a;
                g_ab[cnt * U + j]   = a * s_mu[idx];
                g_aweh[cnt * U + j] = weh;
                g_awdh[cnt * U + j] = wdh;
                n0 += weh; d0 += wdh;
                cnt++;
            }
        }
        for (int k = cnt; k < AMAX; k++) {
            g_asrc[k * U + j] = 0;
            g_aa[k * U + j] = 0.f; g_ab[k * U + j] = 0.f;
            g_aweh[k * U + j] = 0.f; g_awdh[k * U + j] = 0.f;
        }
        g_anum0[j] = n0; g_aden0[j] = d0;
        int m = cnt;
        #pragma unroll
        for (int o = 16; o > 0; o >>= 1) m = max(m, __shfl_xor_sync(FULLM, m, o));
        if (j == 0) g_na = m;
    } else if (tid < 64) {                // sensory lists, column j = tid-32
        int j = tid - 32, cnt = 0;
        float n0 = 0.f, d0 = 0.f;
        for (int i = 0; i < U; i++) {
            int idx = i * U + j;
            if (t_m[idx] != 0 && cnt < SMAX) {
                float a = 0.5f * t_sg[idx];
                float weh = 0.5f * t_w[idx] * t_er[idx];
                float wdh = 0.5f * t_w[idx];
                g_ssrc[cnt * U + j] = i;
                g_sa[cnt * U + j]   = a;
                g_sb[cnt * U + j]   = a * t_mu[idx];
                g_sweh[cnt * U + j] = weh;
                g_swdh[cnt * U + j] = wdh;
                n0 += weh; d0 += wdh;
                cnt++;
            }
        }
        for (int k = cnt; k < SMAX; k++) {
            g_ssrc[k * U + j] = 0;
            g_sa[k * U + j] = 0.f; g_sb[k * U + j] = 0.f;
            g_sweh[k * U + j] = 0.f; g_swdh[k * U + j] = 0.f;
        }
        g_snum0[j] = n0; g_sden0[j] = d0;
        int m = cnt;
        #pragma unroll
        for (int o = 16; o > 0; o >>= 1) m = max(m, __shfl_xor_sync(FULLM, m, o));
        if (j == 0) g_ns = m;
    } else if (tid == 64) {
        // bitmask greedy (S=4): identical assignment to R13's serial greedy.
        const int S = 4;
        int ok = 1, maxR = 0;
        for (int j = 0; j < U && ok; j++) {
            unsigned roundUsed = 0;
            for (int i = 0; i < U; i++) {
                int idx = i * U + j;
                if (s_m[idx] == 0) continue;
                unsigned su   = (unsigned)s_su[i];
                unsigned excl = (su * 0x1111u) & 0xFFFFu;   // rounds blocked by slot use
                unsigned cand = ~roundUsed & ~excl & 0xFFFFu;
                if (!cand) { ok = 0; break; }
                int r = __ffs(cand) - 1;                    // smallest free round
                roundUsed |= 1u << r;
                s_su[i] = (int)(su | (1u << (r & 3)));
                float a   = 0.5f * s_sg[idx];
                float weh = 0.5f * s_w[idx] * s_er[idx];
                float wdh = 0.5f * s_w[idx];
                g_ca2[(r & 3) * U + i] = a;
                g_cb2[(r & 3) * U + i] = a * s_mu[idx];
                g_glane2[r * U + j] = i;
                g_gwe2[r * U + j]  = weh;
                g_gwd2[r * U + j]  = wdh;
                if (r + 1 > maxR) maxR = r + 1;
            }
        }
        g_srcok = ok; g_slots = S; g_rounds2 = maxR;
    }
}

// ---------------------------------------------------------------------------
// Fused producer/consumer kernel (655us layout):
// Blocks 0..127: warps 0,1 = scan (batches 2*bid, 2*bid+1), warps 2,3,6,7 = sens,
//                warps 4,5 exit. Blocks >=128: all 8 warps = sens.
// ---------------------------------------------------------------------------
__device__ void sens_warp(
    int sw, int nw, int warp, int lane, float* smem,
    const float* __restrict__ x,
    const float* __restrict__ d1w, const float* __restrict__ d1b,
    const float* __restrict__ d2b,
    const float* __restrict__ iw,  const float* __restrict__ ib)
{
    float* sh_w2t = smem;                       // [32][132]
    float* sh_h1  = smem + 32 * 132 + warp * 1024;   // [8][128] per warp
    float* sh_in  = smem + 32 * 132 + 8 * 1024 + warp * 256; // [8][32] per warp

    float wa[4], wb[4], bb[4];
    #pragma unroll
    for (int c = 0; c < 4; c++) {
        int k = c * 32 + lane;
        wa[c] = d1w[k]; wb[c] = d1w[128 + k]; bb[c] = d1b[k];
    }
    float dbl = d2b[lane], iwl = iw[lane], ibl = ib[lane];
    float n0 = g_snum0[lane], d0 = g_sden0[lane];
    int ns = g_ns;

    for (int q = sw; q < NTICK; q += nw) {
        int t  = q >> 5;
        int b0 = (q & 31) << 3;

        float2 xv = make_float2(0.f, 0.f);
        if (lane < 8) xv = ((const float2*)x)[(size_t)(b0 + lane) * TDIM + t];

        #pragma unroll
        for (int r = 0; r < 8; r++) {
            float x0 = __shfl_sync(FULLM, xv.x, r);
            float x1 = __shfl_sync(FULLM, xv.y, r);
            #pragma unroll
            for (int c = 0; c < 4; c++) {
                int k = c * 32 + lane;
                sh_h1[r * 128 + k] = fmaxf(fmaf(x0, wa[c], fmaf(x1, wb[c], bb[c])), 0.f);
            }
        }
        __syncwarp();

        float acc[8];
        #pragma unroll
        for (int r = 0; r < 8; r++) acc[r] = dbl;
        #pragma unroll 8
        for (int kq = 0; kq < 32; kq++) {
            float4 w4 = *(const float4*)&sh_w2t[lane * 132 + kq * 4];
            #pragma unroll
            for (int r = 0; r < 8; r++) {
                float4 h4 = *(const float4*)&sh_h1[r * 128 + kq * 4];
                acc[r] = fmaf(h4.x, w4.x, acc[r]);
                acc[r] = fmaf(h4.y, w4.y, acc[r]);
                acc[r] = fmaf(h4.z, w4.z, acc[r]);
                acc[r] = fmaf(h4.w, w4.w, acc[r]);
            }
        }
        #pragma unroll
        for (int r = 0; r < 8; r++) sh_in[r * 32 + lane] = fmaf(acc[r], iwl, ibl);
        __syncwarp();

        float num[8], den[8];
        #pragma unroll
        for (int r = 0; r < 8; r++) { num[r] = n0; den[r] = d0; }
        for (int k = 0; k < ns; k++) {
            int   src = g_ssrc[k * U + lane];
            float a   = g_sa[k * U + lane];
            float b   = g_sb[k * U + lane];
            float weh = g_sweh[k * U + lane];
            float wdh = g_swdh[k * U + lane];
            #pragma unroll
            for (int r = 0; r < 8; r++) {
                float tk = tanhf_a(fmaf(a, sh_in[r * 32 + src], -b));
                num[r] = fmaf(weh, tk, num[r]);
                den[r] = fmaf(wdh, tk, den[r]);
            }
        }
        #pragma unroll
        for (int r = 0; r < 8; r++)
            g_sens[((size_t)(b0 + r) * TDIM + t) * U + lane] = make_float2(num[r], den[r]);

        __threadfence();
        if (lane == 0) atomicAdd(&g_cnt[t], 1);
        __syncwarp();
    }
}

__device__ __forceinline__ void verify8(int base) {
    for (;;) {
        int ok = 1;
        #pragma unroll
        for (int i = 0; i < 8; i++)
            ok &= (ld_acq(&g_cnt[base + i]) == 32);
        if (ok) return;
        __nanosleep(200);
    }
}

// Source-side tanh scan: lane computes SLOTS tanh from LOCAL v (no shfl wait),
// then one gather wave of NR shfls delivers finished tanh values.
template <int SLOTS, int NR>
__device__ void scan_src(
    int lane, int batch,
    const float* __restrict__ gleak, const float* __restrict__ vleak,
    const float* __restrict__ cm,
    const float* __restrict__ ow, const float* __restrict__ ob,
    float* __restrict__ out)
{
    float gl   = gleak[lane];
    float cmt  = cm[lane] * (float)UNF;
    float gv   = gl * vleak[lane];
    float dcst = cmt + gl + EPSV + g_aden0[lane];
    float ncst = g_anum0[lane];

    float ca[SLOTS], cb[SLOTS];
    #pragma unroll
    for (int s = 0; s < SLOTS; s++) {
        ca[s] = g_ca2[s * U + lane];
        cb[s] = g_cb2[s * U + lane];
    }
    int gl_[NR]; float gwe[NR], gwd[NR];
    #pragma unroll
    for (int r = 0; r < NR; r++) {
        gl_[r] = g_glane2[r * U + lane];
        gwe[r] = g_gwe2[r * U + lane];
        gwd[r] = g_gwd2[r * U + lane];
    }

    const float2* sp = g_sens + (size_t)batch * TDIM * U + lane;

    verify8(0);
    float2 sv = sp[0];
    float v = 0.f;

    for (int t = 0; t < TDIM; t++) {
        if ((t & 7) == 0 && t + 8 < TDIM) verify8(t + 8);
        int tn = (t + 1 < TDIM) ? (t + 1) : t;
        float2 nxt = sp[(size_t)tn * U];

        float nb = sv.x + ncst;
        float db = sv.y + dcst;

        #pragma unroll
        for (int u = 0; u < UNF; u++) {
            float p = fmaf(cmt, v, gv);
            // local tanh of out-edges: args ready at cycle 0
            float tv[SLOTS];
            #pragma unroll
            for (int s = 0; s < SLOTS; s++)
                tv[s] = tanhf_a(fmaf(ca[s], v, -cb[s]));
            // one gather wave: finished tanh values from source lanes
            float tk[NR];
            #pragma unroll
            for (int r = 0; r < NR; r++)
                tk[r] = __shfl_sync(FULLM, tv[r % SLOTS], gl_[r]);

            float nch[4], dch[4];
            nch[0] = p + nb; nch[1] = 0.f; nch[2] = 0.f; nch[3] = 0.f;
            dch[0] = db;     dch[1] = 0.f; dch[2] = 0.f; dch[3] = 0.f;
            #pragma unroll
            for (int r = 0; r < NR; r++) {
                nch[r & 3] = fmaf(gwe[r], tk[r], nch[r & 3]);
                dch[r & 3] = fmaf(gwd[r], tk[r], dch[r & 3]);
            }
            float num = (nch[0] + nch[1]) + (nch[2] + nch[3]);
            float den = (dch[0] + dch[1]) + (dch[2] + dch[3]);
            v = num * rcpf(den);
        }
        sv = nxt;
    }

    if (lane == 0) out[batch] = fmaf(v, ow[0], ob[0]);
}

// R4 fallback body
template <int NA>
__device__ void scan_body(
    int lane, int batch,
    const float* __restrict__ gleak, const float* __restrict__ vleak,
    const float* __restrict__ cm,
    const float* __restrict__ ow, const float* __restrict__ ob,
    float* __restrict__ out)
{
    float gl   = gleak[lane];
    float cmt  = cm[lane] * (float)UNF;
    float gv   = gl * vleak[lane];
    float dcst = cmt + gl + EPSV + g_aden0[lane];
    float ncst = g_anum0[lane];

    int src[NA]; float a[NA], b[NA], weh[NA], wdh[NA];
    #pragma unroll
    for (int k = 0; k < NA; k++) {
        src[k] = g_asrc[k * U + lane];
        a[k]   = g_aa[k * U + lane];
        b[k]   = g_ab[k * U + lane];
        weh[k] = g_aweh[k * U + lane];
        wdh[k] = g_awdh[k * U + lane];
    }

    const float2* sp = g_sens + (size_t)batch * TDIM * U + lane;

    verify8(0);
    float2 sv = sp[0];
    float v = 0.f;

    for (int t = 0; t < TDIM; t++) {
        if ((t & 7) == 0 && t + 8 < TDIM) verify8(t + 8);
        int tn = (t + 1 < TDIM) ? (t + 1) : t;
        float2 nxt = sp[(size_t)tn * U];

        float nb = sv.x + ncst;
        float db = sv.y + dcst;

        #pragma unroll
        for (int u = 0; u < UNF; u++) {
            float p = fmaf(cmt, v, gv);
            float tk[NA];
            #pragma unroll
            for (int k = 0; k < NA; k++) {
                float vs = __shfl_sync(FULLM, v, src[k]);
                tk[k] = tanhf_a(fmaf(a[k], vs, -b[k]));
            }
            float nch[4], dch[4];
            nch[0] = p + nb; nch[1] = 0.f; nch[2] = 0.f; nch[3] = 0.f;
            dch[0] = db;     dch[1] = 0.f; dch[2] = 0.f; dch[3] = 0.f;
            #pragma unroll
            for (int k = 0; k < NA; k++) {
                nch[k & 3] = fmaf(weh[k], tk[k], nch[k & 3]);
                dch[k & 3] = fmaf(wdh[k], tk[k], dch[k & 3]);
            }
            float num = (nch[0] + nch[1]) + (nch[2] + nch[3]);
            float den = (dch[0] + dch[1]) + (dch[2] + dch[3]);
            v = num * rcpf(den);
        }
        sv = nxt;
    }

    if (lane == 0) out[batch] = fmaf(v, ow[0], ob[0]);
}

__global__ void __launch_bounds__(256) fused_kernel(
    const float* __restrict__ x,
    const float* __restrict__ d1w, const float* __restrict__ d1b,
    const float* __restrict__ d2w, const float* __restrict__ d2b,
    const float* __restrict__ iw,  const float* __restrict__ ib,
    const float* __restrict__ gleak, const float* __restrict__ vleak,
    const float* __restrict__ cm,
    const float* __restrict__ ow, const float* __restrict__ ob,
    float* __restrict__ out)
{
    extern __shared__ float smem[];
    int tid = threadIdx.x, warp = tid >> 5, lane = tid & 31;

    for (int i = tid; i < 128 * 32; i += 256) {
        int k = i >> 5, j = i & 31;
        smem[j * 132 + k] = d2w[i];
    }
    __syncthreads();

    bool scanBlk = (blockIdx.x < 128);
    if (scanBlk && warp < 2) {
        int batch = blockIdx.x * 2 + warp;
        int ok = g_srcok, rr = g_rounds2;
        if (ok) {
            if      (rr <= 8)  scan_src<4, 8 >(lane, batch, gleak, vleak, cm, ow, ob, out);
            else if (rr <= 12) scan_src<4, 12>(lane, batch, gleak, vleak, cm, ow, ob, out);
            else               scan_src<4, 16>(lane, batch, gleak, vleak, cm, ow, ob, out);
        } else {
            int na = g_na;
            if      (na <= 4)  scan_body<4 >(lane, batch, gleak, vleak, cm, ow, ob, out);
            else if (na <= 6)  scan_body<6 >(lane, batch, gleak, vleak, cm, ow, ob, out);
            else if (na <= 8)  scan_body<8 >(lane, batch, gleak, vleak, cm, ow, ob, out);
            else if (na <= 10) scan_body<10>(lane, batch, gleak, vleak, cm, ow, ob, out);
            else if (na <= 12) scan_body<12>(lane, batch, gleak, vleak, cm, ow, ob, out);
            else               scan_body<18>(lane, batch, gleak, vleak, cm, ow, ob, out);
        }
    } else if (scanBlk) {
        if (warp == 4 || warp == 5) return;     // keep SMSP 0/1 for scan warps
        int idx = (warp >= 6) ? (warp - 4) : (warp - 2);  // {2,3,6,7} -> {0,1,2,3}
        int sw = blockIdx.x * 4 + idx;
        int nw = 128 * 4 + (gridDim.x - 128) * 8;
        sens_warp(sw, nw, warp, lane, smem, x, d1w, d1b, d2b, iw, ib);
    } else {
        int sw = 128 * 4 + (blockIdx.x - 128) * 8 + warp;
        int nw = 128 * 4 + (gridDim.x - 128) * 8;
        sens_warp(sw, nw, warp, lane, smem, x, d1w, d1b, d2b, iw, ib);
    }
}

// ---------------------------------------------------------------------------
extern "C" void kernel_launch(void* const* d_in, const int* in_sizes, int n_in,
                              void* d_out, int out_size)
{
    const float* x    = (const float*)d_in[0];
    const float* d1w  = (const float*)d_in[1];
    const float* d1b  = (const float*)d_in[2];
    const float* d2w  = (const float*)d_in[3];
    const float* d2b  = (const float*)d_in[4];
    const float* iw   = (const float*)d_in[5];
    const float* ib   = (const float*)d_in[6];
    const float* ow   = (const float*)d_in[7];
    const float* ob   = (const float*)d_in[8];
    const float* gle  = (const float*)d_in[9];
    const float* vle  = (const float*)d_in[10];
    const float* cmv  = (const float*)d_in[11];
    const float* wsyn = (const float*)d_in[12];
    const float* muv  = (const float*)d_in[13];
    const float* sgv  = (const float*)d_in[14];
    const float* erv  = (const float*)d_in[15];
    const float* swv  = (const float*)d_in[16];
    const float* smuv = (const float*)d_in[17];
    const float* ssgv = (const float*)d_in[18];
    const float* serv = (const float*)d_in[19];
    const int*   spm  = (const int*)d_in[20];
    const int*   ssm  = (const int*)d_in[21];

    int nsm = 148;
    cudaDeviceGetAttribute(&nsm, cudaDevAttrMultiProcessorCount, 0);
    int blocks = (nsm > 128) ? nsm : 129;   // >=129 so at least 1 all-sens block

    const int smemBytes = (32 * 132 + 8 * 1024 + 8 * 256) * sizeof(float); // ~57.5 KB
    cudaFuncSetAttribute(fused_kernel, cudaFuncAttributeMaxDynamicSharedMemorySize, smemBytes);

    setup_kernel<<<1, 1024>>>(spm, wsyn, muv, sgv, erv, ssm, swv, smuv, ssgv, serv);
    fused_kernel<<<blocks, 256, smemBytes>>>(x, d1w, d1b, d2w, d2b, iw, ib,
                                             gle, vle, cmv, ow, ob, (float*)d_out);
}